// round 1
// baseline (speedup 1.0000x reference)
#include <cuda_runtime.h>
#include <math.h>
#include <stdint.h>

// ---------------------------------------------------------------------------
// tcnn HashGrid encode: coords [N,3] in [0,1], table [16, 2^19, 2] f32.
// Output [N, 32] f32 (16 levels x 2 feats, trilinear interpolation).
// Levels 0-4: dense indexing (res^3 <= 2^19). Levels 5-15: spatial hash.
// ---------------------------------------------------------------------------

namespace {
constexpr int      NLV    = 16;
constexpr unsigned TSZ    = 1u << 19;
constexpr unsigned TMASK  = TSZ - 1u;
constexpr unsigned PRIME2 = 2654435761u;
constexpr unsigned PRIME3 = 805459861u;
}

struct LevelMeta {
    float    scale;   // base * s^l - 1 (cast to f32, as reference does)
    unsigned res;     // ceil(scale) + 1
    unsigned res2;    // res*res
    unsigned hashed;  // res^3 > T ?
};

__device__ LevelMeta g_meta[NLV];

// Compute per-level constants in fp64 (matches Python's `s ** l` + ceil).
// Launched every kernel_launch call: deterministic, capturable, ~free.
__global__ void hg_init_meta() {
    int l = threadIdx.x;
    if (l < NLV) {
        double sc = 16.0 * pow(1.4472692012786865, (double)l) - 1.0;
        unsigned res = (unsigned)ceil(sc) + 1u;
        LevelMeta m;
        m.scale  = (float)sc;
        m.res    = res;
        m.res2   = res * res;
        m.hashed = ((double)res * (double)res * (double)res > (double)TSZ) ? 1u : 0u;
        g_meta[l] = m;
    }
}

// Block = 512 threads = 16 warps. Warp w handles level w for 32 points.
// Per-level constants are warp-uniform; dense/hash branch is warp-coherent.
// Results staged through padded smem so the final global store is one
// contiguous, fully-coalesced 4KB burst per block.
__global__ __launch_bounds__(512) void hg_encode(
    const float*  __restrict__ coords,
    const float2* __restrict__ table,
    float*        __restrict__ out,
    int n_points)
{
    __shared__ float s_out[32][33];   // [point][feat], +1 pad: conflict-free

    const int lane  = threadIdx.x & 31;
    const int level = threadIdx.x >> 5;
    const int p     = blockIdx.x * 32 + lane;

    if (p < n_points) {
        const float x = coords[3 * p + 0];
        const float y = coords[3 * p + 1];
        const float z = coords[3 * p + 2];

        const LevelMeta m = g_meta[level];

        const float px = x * m.scale + 0.5f;
        const float py = y * m.scale + 0.5f;
        const float pz = z * m.scale + 0.5f;
        const float fx = floorf(px), fy = floorf(py), fz = floorf(pz);
        const float wx = px - fx,    wy = py - fy,    wz = pz - fz;
        const unsigned gx = (unsigned)fx, gy = (unsigned)fy, gz = (unsigned)fz;

        unsigned idx0, idx1, idx2, idx3, idx4, idx5, idx6, idx7;
        if (m.hashed) {
            const unsigned hx0 = gx,           hx1 = gx + 1u;
            const unsigned hy0 = gy * PRIME2,  hy1 = hy0 + PRIME2;
            const unsigned hz0 = gz * PRIME3,  hz1 = hz0 + PRIME3;
            idx0 = (hx0 ^ hy0 ^ hz0) & TMASK;
            idx1 = (hx0 ^ hy0 ^ hz1) & TMASK;
            idx2 = (hx0 ^ hy1 ^ hz0) & TMASK;
            idx3 = (hx0 ^ hy1 ^ hz1) & TMASK;
            idx4 = (hx1 ^ hy0 ^ hz0) & TMASK;
            idx5 = (hx1 ^ hy0 ^ hz1) & TMASK;
            idx6 = (hx1 ^ hy1 ^ hz0) & TMASK;
            idx7 = (hx1 ^ hy1 ^ hz1) & TMASK;
        } else {
            const unsigned R1  = m.res - 1u;
            const unsigned cx0 = min(gx, R1),              cx1 = min(gx + 1u, R1);
            const unsigned cy0 = min(gy, R1) * m.res,      cy1 = min(gy + 1u, R1) * m.res;
            const unsigned cz0 = min(gz, R1) * m.res2,     cz1 = min(gz + 1u, R1) * m.res2;
            idx0 = cx0 + cy0 + cz0;
            idx1 = cx0 + cy0 + cz1;
            idx2 = cx0 + cy1 + cz0;
            idx3 = cx0 + cy1 + cz1;
            idx4 = cx1 + cy0 + cz0;
            idx5 = cx1 + cy0 + cz1;
            idx6 = cx1 + cy1 + cz0;
            idx7 = cx1 + cy1 + cz1;
        }

        const float2* __restrict__ tbl = table + (size_t)level * (size_t)TSZ;
        // Issue all 8 gathers before consuming any (MLP = 8).
        const float2 v0 = __ldg(tbl + idx0);
        const float2 v1 = __ldg(tbl + idx1);
        const float2 v2 = __ldg(tbl + idx2);
        const float2 v3 = __ldg(tbl + idx3);
        const float2 v4 = __ldg(tbl + idx4);
        const float2 v5 = __ldg(tbl + idx5);
        const float2 v6 = __ldg(tbl + idx6);
        const float2 v7 = __ldg(tbl + idx7);

        const float ix = 1.0f - wx, iy = 1.0f - wy, iz = 1.0f - wz;
        const float a00 = ix * iy, a01 = ix * wy, a10 = wx * iy, a11 = wx * wy;
        const float w0 = a00 * iz, w1 = a00 * wz;   // (dx,dy,dz)=(0,0,0),(0,0,1)
        const float w2 = a01 * iz, w3 = a01 * wz;   // (0,1,0),(0,1,1)
        const float w4 = a10 * iz, w5 = a10 * wz;   // (1,0,0),(1,0,1)
        const float w6 = a11 * iz, w7 = a11 * wz;   // (1,1,0),(1,1,1)

        float f0 = w0 * v0.x;  float f1 = w0 * v0.y;
        f0 += w1 * v1.x;       f1 += w1 * v1.y;
        f0 += w2 * v2.x;       f1 += w2 * v2.y;
        f0 += w3 * v3.x;       f1 += w3 * v3.y;
        f0 += w4 * v4.x;       f1 += w4 * v4.y;
        f0 += w5 * v5.x;       f1 += w5 * v5.y;
        f0 += w6 * v6.x;       f1 += w6 * v6.y;
        f0 += w7 * v7.x;       f1 += w7 * v7.y;

        s_out[lane][2 * level + 0] = f0;
        s_out[lane][2 * level + 1] = f1;
    }
    __syncthreads();

    // Coalesced writeback: 512 threads x float2 = 4KB contiguous per block.
    const int t  = threadIdx.x;
    const int pp = t >> 4;          // point within block: 0..31
    const int c  = (t & 15) * 2;    // feature column: 0,2,...,30
    const int gp = blockIdx.x * 32 + pp;
    if (gp < n_points) {
        const float a = s_out[pp][c];
        const float b = s_out[pp][c + 1];
        float2* o = reinterpret_cast<float2*>(out + (size_t)gp * 32 + c);
        *o = make_float2(a, b);
    }
}

extern "C" void kernel_launch(void* const* d_in, const int* in_sizes, int n_in,
                              void* d_out, int out_size) {
    const float*  coords = (const float*)d_in[0];   // [N, 3] f32
    const float2* table  = (const float2*)d_in[1];  // [16, 2^19, 2] f32
    float*        out    = (float*)d_out;           // [N, 32] f32
    const int n_points = in_sizes[0] / 3;

    hg_init_meta<<<1, 32>>>();
    const int blocks = (n_points + 31) / 32;
    hg_encode<<<blocks, 512>>>(coords, table, out, n_points);
}